// round 14
// baseline (speedup 1.0000x reference)
#include <cuda_runtime.h>
#include <cstdint>
#include <cstddef>

#define T_STEPS 2048
#define BATCH   64
#define HID     256
#define NLAYER  2
#define MROWS   (T_STEPS * BATCH)       // 131072

// h_s smem swizzle: 8 slices (32 k each); slice stride 524 floats,
// b-half offset 260, row stride 8 -> every LDS.128 resolves in 2 phases.
#define HS_SL   524
#define HS_HALF 260

// ---------------- scratch (static device memory; no allocation APIs) -------
__device__ float    g_pre[(size_t)NLAYER * MROWS * 1024];   // 1 GiB
__device__ float    g_h2[NLAYER][2][4][256 * 16];           // [l][buf][bR][j*16+b']
__device__ unsigned g_flag[NLAYER * 4][16][32];             // per-producer flags

// ---------------- packed fp32x2 helpers ------------------------------------
__device__ __forceinline__ unsigned long long pack2(float x, float y) {
    unsigned long long r;
    asm("mov.b64 %0, {%1, %2};" : "=l"(r) : "f"(x), "f"(y));
    return r;
}
__device__ __forceinline__ void unpack2(unsigned long long v, float& x, float& y) {
    asm("mov.b64 {%0, %1}, %2;" : "=f"(x), "=f"(y) : "l"(v));
}
__device__ __forceinline__ void fma2(unsigned long long& d, unsigned long long a,
                                     unsigned long long b) {
    asm("fma.rn.f32x2 %0, %1, %2, %0;" : "+l"(d) : "l"(a), "l"(b));
}
__device__ __forceinline__ unsigned long long add2(unsigned long long a,
                                                   unsigned long long b) {
    unsigned long long r;
    asm("add.rn.f32x2 %0, %1, %2;" : "=l"(r) : "l"(a), "l"(b));
    return r;
}

// MUFU-path activations (independent of compiler fast-math flags)
__device__ __forceinline__ float fast_sigmoid(float x) {
    float e, r;
    asm("ex2.approx.f32 %0, %1;" : "=f"(e) : "f"(-1.4426950408889634f * x));
    asm("rcp.approx.f32 %0, %1;" : "=f"(r) : "f"(1.0f + e));
    return r;
}
__device__ __forceinline__ float fast_tanh(float x) {
    float e, r;
    asm("ex2.approx.f32 %0, %1;" : "=f"(e) : "f"(2.8853900817779268f * x));
    asm("rcp.approx.f32 %0, %1;" : "=f"(r) : "f"(1.0f + e));
    return 1.0f - 2.0f * r;
}

// ---------------- kernel 1: pre[l,t,b,:] = x[t,b,:] @ Wx[l] + b[l] ---------
__global__ __launch_bounds__(256, 2) void k_pre(const float* __restrict__ x,
                                                const float* __restrict__ W,
                                                const float* __restrict__ bias) {
    __shared__ __align__(16) float As[32 * 132];
    __shared__ __align__(16) float Bs[32 * 128];

    // reset all producer flags (graph replay safe; runs before k_rec)
    if (blockIdx.x == 0 && threadIdx.x < NLAYER * 4 * 16)
        g_flag[threadIdx.x >> 4][threadIdx.x & 15][0] = 0u;

    int bid  = blockIdx.x;
    int l    = bid >> 13;
    int rem  = bid & 8191;
    int mt   = rem >> 3;
    int nt   = rem & 7;
    int row0 = mt << 7;
    int col0 = nt << 7;
    int tid  = threadIdx.x;
    int tm   = tid >> 4;
    int tn   = tid & 15;

    const float* Wl = W + (size_t)l * 512 * 1024;

    unsigned long long acc[8][4];
#pragma unroll
    for (int i = 0; i < 8; i++)
#pragma unroll
        for (int j = 0; j < 4; j++) acc[i][j] = 0ULL;

    for (int kc = 0; kc < 256; kc += 32) {
#pragma unroll
        for (int i = 0; i < 4; i++) {
            int aidx = tid + i * 256;
            int m    = aidx >> 3;
            int k4   = (aidx & 7) << 2;
            float4 v = *(const float4*)&x[(size_t)(row0 + m) * 256 + kc + k4];
            As[(k4 + 0) * 132 + m] = v.x;
            As[(k4 + 1) * 132 + m] = v.y;
            As[(k4 + 2) * 132 + m] = v.z;
            As[(k4 + 3) * 132 + m] = v.w;
        }
#pragma unroll
        for (int i = 0; i < 4; i++) {
            int kk = (tid >> 5) + i * 8;
            int n4 = (tid & 31) << 2;
            *(float4*)&Bs[kk * 128 + n4] =
                *(const float4*)&Wl[(size_t)(kc + kk) * 1024 + col0 + n4];
        }
        __syncthreads();

#pragma unroll
        for (int k = 0; k < 32; k++) {
            float4 a0 = *(const float4*)&As[k * 132 + tm * 8];
            float4 a1 = *(const float4*)&As[k * 132 + tm * 8 + 4];
            ulonglong2 bb01 = *(const ulonglong2*)&Bs[k * 128 + tn * 8];
            ulonglong2 bb23 = *(const ulonglong2*)&Bs[k * 128 + tn * 8 + 4];
            float av[8] = {a0.x, a0.y, a0.z, a0.w, a1.x, a1.y, a1.z, a1.w};
#pragma unroll
            for (int i = 0; i < 8; i++) {
                unsigned long long a2 = pack2(av[i], av[i]);
                fma2(acc[i][0], a2, bb01.x);
                fma2(acc[i][1], a2, bb01.y);
                fma2(acc[i][2], a2, bb23.x);
                fma2(acc[i][3], a2, bb23.y);
            }
        }
        __syncthreads();
    }

    float bv[8];
#pragma unroll
    for (int j = 0; j < 8; j++) bv[j] = bias[l * 1024 + col0 + tn * 8 + j];
#pragma unroll
    for (int i = 0; i < 8; i++) {
        float o[8];
#pragma unroll
        for (int j = 0; j < 4; j++) unpack2(acc[i][j], o[2 * j], o[2 * j + 1]);
#pragma unroll
        for (int j = 0; j < 8; j++) o[j] += bv[j];
        size_t base = ((size_t)l * MROWS + row0 + tm * 8 + i) * 1024 + col0 + tn * 8;
        __stcs((float4*)&g_pre[base],     make_float4(o[0], o[1], o[2], o[3]));
        __stcs((float4*)&g_pre[base + 4], make_float4(o[4], o[5], o[6], o[7]));
    }
}

// ---------------- kernel 2: persistent recurrence ---------------------------
// 128 CTAs = 2 layers x 4 b-groups (16 b) x 16 hcol-groups (16 hcols).
// Sync via 16 per-producer release flags per (layer,b-group); each of the
// 8 warps polls 2 producers and copies that producer's contiguous 1 KB
// h-chunk as soon as it lands (pipelined staging).
__global__ __launch_bounds__(256, 1) void k_rec(const float* __restrict__ h0,
                                                const float* __restrict__ c0,
                                                const float* __restrict__ W,
                                                float* __restrict__ out) {
    __shared__ __align__(16) float h_s[8 * HS_SL];   // 16768 B

    int bid   = blockIdx.x;
    int l     = bid >> 6;
    int r     = bid & 63;
    int bR    = r >> 4;                 // b-group 0..3
    int hR    = r & 15;                 // hcol-group 0..15
    int b0    = bR << 4;
    int hcol0 = hR << 4;
    int tid   = threadIdx.x;
    int o     = tid >> 5;               // warp
    int lane  = tid & 31;
    int ks    = lane >> 2;              // 0..7 (32-k slice)
    int ng    = lane & 3;
    int hc_in = (o << 1) | (ng & 1);    // 0..15
    int hcol  = hcol0 + hc_in;          // global hidden index
    int bhalf = ng >> 1;
    int bq8   = bhalf << 3;
    int b_pw  = b0 + bq8 + ks;          // this lane's pointwise batch row
    int grp   = l * 4 + bR;
    unsigned* myflag = &g_flag[grp][hR][0];

    // ---- W slice -> registers (persistent across all 2048 steps) ----
    unsigned long long wfi[32], wgo[32];
    {
        const float* Whl = W + (size_t)l * 512 * 1024 + (size_t)256 * 1024;
#pragma unroll
        for (int kk = 0; kk < 32; kk++) {
            const float* wr = Whl + (size_t)((ks << 5) + kk) * 1024 + hcol;
            wfi[kk] = pack2(wr[0], wr[256]);     // (f, i)
            wgo[kk] = pack2(wr[512], wr[768]);   // (g, o)
        }
    }

    // stage h0 slice [j][b'=0..15] -> swizzled smem
    const float* h0l = h0 + l * BATCH * HID;
    for (int i = tid; i < 4096; i += 256) {
        int j  = i >> 4;
        int bp = i & 15;
        int nh = bp >> 3;
        h_s[(j >> 5) * HS_SL + nh * HS_HALF + (j & 31) * 8 + (bp & 7)] =
            h0l[(b0 + bp) * 256 + j];
    }
    float c = c0[l * BATCH * HID + b_pw * 256 + hcol];
    float h_cur = 0.0f;
    __syncthreads();

    const float* hp = h_s + ks * HS_SL + bhalf * HS_HALF;

    for (int t = 0; t < T_STEPS; t++) {
        // prefetch pre-activations (independent of everything below)
        size_t prow = ((size_t)l * MROWS + (size_t)t * BATCH + b_pw) * 1024 + hcol;
        float pf = __ldcs(&g_pre[prow]);
        float pi = __ldcs(&g_pre[prow + 256]);
        float pg = __ldcs(&g_pre[prow + 512]);
        float po = __ldcs(&g_pre[prow + 768]);

        // 8b partial dot over this thread's 32-k slice; W from registers
        unsigned long long fi[8], go[8];
#pragma unroll
        for (int i = 0; i < 8; i++) { fi[i] = 0ULL; go[i] = 0ULL; }
#pragma unroll
        for (int kk = 0; kk < 32; kk++) {
            float4 hv0 = *(const float4*)&hp[kk << 3];
            float4 hv1 = *(const float4*)&hp[(kk << 3) + 4];
            float hh[8] = {hv0.x, hv0.y, hv0.z, hv0.w,
                           hv1.x, hv1.y, hv1.z, hv1.w};
#pragma unroll
            for (int bi = 0; bi < 8; bi++) {
                unsigned long long a2 = pack2(hh[bi], hh[bi]);
                fma2(fi[bi], a2, wfi[kk]);
                fma2(go[bi], a2, wgo[kk]);
            }
        }

        // reduce-scatter over ks (lane strides 16,8,4): lane ends with bi=ks
#pragma unroll
        for (int rd = 0; rd < 3; rd++) {
            int stride = 16 >> rd;     // 16, 8, 4
            int half   = 4 >> rd;      // 4, 2, 1
            bool hi = (lane & stride) != 0;
#pragma unroll
            for (int i = 0; i < 4; i++) {
                if (i < half) {
                    unsigned long long sf = hi ? fi[i] : fi[i + half];
                    unsigned long long kf = hi ? fi[i + half] : fi[i];
                    fi[i] = add2(kf, __shfl_xor_sync(0xFFFFFFFFu, sf, stride));
                    unsigned long long sg = hi ? go[i] : go[i + half];
                    unsigned long long kg = hi ? go[i + half] : go[i];
                    go[i] = add2(kg, __shfl_xor_sync(0xFFFFFFFFu, sg, stride));
                }
            }
        }

        // pointwise (every lane owns one (b_pw, hcol)) — MUFU activations
        float af, ai_, ag, ao;
        unpack2(fi[0], af, ai_);
        unpack2(go[0], ag, ao);
        float gf  = fast_sigmoid(af + pf);
        float gi  = fast_sigmoid(ai_ + pi);
        float gg  = fast_tanh(ag + pg);
        float go_ = fast_sigmoid(ao + po);
        c     = gf * c + gi * gg;
        h_cur = go_ * fast_tanh(c);

        int wb = 1 - (t & 1);
        g_h2[l][wb][bR][hcol * 16 + bq8 + ks] = h_cur;
        if (l == 1) out[(size_t)t * BATCH * HID + b_pw * 256 + hcol] = h_cur;

        if (t == T_STEPS - 1) break;

        __syncthreads();                 // all local warps done reading h_s
        if (tid == 0) {                  // publish this CTA's chunk
            asm volatile("st.release.gpu.global.u32 [%0], %1;"
                         :: "l"(myflag), "r"((unsigned)(t + 1)) : "memory");
        }

        // pipelined staging: warp o polls producers o and o+8, copies 1 KB each
        const float* hbase = g_h2[l][wb][bR];
#pragma unroll
        for (int pp = 0; pp < 2; pp++) {
            int p = o + (pp << 3);
            const unsigned* fl = &g_flag[grp][p][0];
            unsigned v;
            do {
                asm volatile("ld.acquire.gpu.global.u32 %0, [%1];"
                             : "=r"(v) : "l"(fl));
            } while (v < (unsigned)(t + 1));
            const float4* src = (const float4*)&hbase[p * 256];   // 16 rows x 16 b'
#pragma unroll
            for (int q = 0; q < 2; q++) {
                int m   = lane + (q << 5);       // 0..63 float4
                int j   = (p << 4) + (m >> 2);   // global hidden row
                int bp4 = m & 3;
                float4 v4 = __ldcg(&src[m]);
                *(float4*)&h_s[(j >> 5) * HS_SL + (bp4 >> 1) * HS_HALF
                               + (j & 31) * 8 + (bp4 & 1) * 4] = v4;
            }
        }
        __syncthreads();
    }

    size_t OUTH = (size_t)T_STEPS * BATCH * HID;
    out[OUTH + (size_t)l * BATCH * HID + b_pw * 256 + hcol]                = h_cur;
    out[OUTH + (size_t)NLAYER * BATCH * HID + (size_t)l * BATCH * HID
        + b_pw * 256 + hcol]                                                = c;
}

// ---------------- launch ----------------------------------------------------
extern "C" void kernel_launch(void* const* d_in, const int* in_sizes, int n_in,
                              void* d_out, int out_size) {
    const float* x    = (const float*)d_in[0];
    const float* h0   = (const float*)d_in[1];
    const float* c0   = (const float*)d_in[2];
    const float* W    = (const float*)d_in[3];
    const float* bias = (const float*)d_in[4];
    float* out = (float*)d_out;

    k_pre<<<NLAYER * (MROWS / 128) * (1024 / 128), 256>>>(x, W, bias);
    k_rec<<<NLAYER * 64, 256>>>(h0, c0, W, out);
}

// round 15
// speedup vs baseline: 1.1486x; 1.1486x over previous
#include <cuda_runtime.h>
#include <cstdint>
#include <cstddef>

#define T_STEPS 2048
#define BATCH   64
#define HID     256
#define NLAYER  2
#define MROWS   (T_STEPS * BATCH)       // 131072

// h_s smem: 8 slices (32 k each) of 8 b; slice stride 260 floats
// (= 65 quads = 1 mod 32) -> dot LDS.128: 8 distinct quads, 1 phase.
#define HS_SL   260

// ---------------- scratch (static device memory; no allocation APIs) -------
__device__ float    g_pre[(size_t)NLAYER * MROWS * 1024];   // 1 GiB
__device__ float    g_h2[NLAYER][2][8][256 * 8];            // [l][buf][bR][j*8+b']
__device__ unsigned g_cnt2[NLAYER * 8][32];                 // padded counters

// ---------------- packed fp32x2 helpers ------------------------------------
__device__ __forceinline__ unsigned long long pack2(float x, float y) {
    unsigned long long r;
    asm("mov.b64 %0, {%1, %2};" : "=l"(r) : "f"(x), "f"(y));
    return r;
}
__device__ __forceinline__ void unpack2(unsigned long long v, float& x, float& y) {
    asm("mov.b64 {%0, %1}, %2;" : "=f"(x), "=f"(y) : "l"(v));
}
__device__ __forceinline__ void fma2(unsigned long long& d, unsigned long long a,
                                     unsigned long long b) {
    asm("fma.rn.f32x2 %0, %1, %2, %0;" : "+l"(d) : "l"(a), "l"(b));
}
__device__ __forceinline__ unsigned long long add2(unsigned long long a,
                                                   unsigned long long b) {
    unsigned long long r;
    asm("add.rn.f32x2 %0, %1, %2;" : "=l"(r) : "l"(a), "l"(b));
    return r;
}

// MUFU-path activations (independent of compiler fast-math flags)
__device__ __forceinline__ float fast_sigmoid(float x) {
    float e, r;
    asm("ex2.approx.f32 %0, %1;" : "=f"(e) : "f"(-1.4426950408889634f * x));
    asm("rcp.approx.f32 %0, %1;" : "=f"(r) : "f"(1.0f + e));
    return r;
}
__device__ __forceinline__ float fast_tanh(float x) {
    float e, r;
    asm("ex2.approx.f32 %0, %1;" : "=f"(e) : "f"(2.8853900817779268f * x));
    asm("rcp.approx.f32 %0, %1;" : "=f"(r) : "f"(1.0f + e));
    return 1.0f - 2.0f * r;
}

// ---------------- kernel 1: pre[l,t,b,:] = x[t,b,:] @ Wx[l] + b[l] ---------
__global__ __launch_bounds__(256, 2) void k_pre(const float* __restrict__ x,
                                                const float* __restrict__ W,
                                                const float* __restrict__ bias) {
    __shared__ __align__(16) float As[32 * 132];
    __shared__ __align__(16) float Bs[32 * 128];

    if (blockIdx.x == 0 && threadIdx.x < NLAYER * 8)
        g_cnt2[threadIdx.x][0] = 0u;

    int bid  = blockIdx.x;
    int l    = bid >> 13;
    int rem  = bid & 8191;
    int mt   = rem >> 3;
    int nt   = rem & 7;
    int row0 = mt << 7;
    int col0 = nt << 7;
    int tid  = threadIdx.x;
    int tm   = tid >> 4;
    int tn   = tid & 15;

    const float* Wl = W + (size_t)l * 512 * 1024;

    unsigned long long acc[8][4];
#pragma unroll
    for (int i = 0; i < 8; i++)
#pragma unroll
        for (int j = 0; j < 4; j++) acc[i][j] = 0ULL;

    for (int kc = 0; kc < 256; kc += 32) {
#pragma unroll
        for (int i = 0; i < 4; i++) {
            int aidx = tid + i * 256;
            int m    = aidx >> 3;
            int k4   = (aidx & 7) << 2;
            float4 v = *(const float4*)&x[(size_t)(row0 + m) * 256 + kc + k4];
            As[(k4 + 0) * 132 + m] = v.x;
            As[(k4 + 1) * 132 + m] = v.y;
            As[(k4 + 2) * 132 + m] = v.z;
            As[(k4 + 3) * 132 + m] = v.w;
        }
#pragma unroll
        for (int i = 0; i < 4; i++) {
            int kk = (tid >> 5) + i * 8;
            int n4 = (tid & 31) << 2;
            *(float4*)&Bs[kk * 128 + n4] =
                *(const float4*)&Wl[(size_t)(kc + kk) * 1024 + col0 + n4];
        }
        __syncthreads();

#pragma unroll
        for (int k = 0; k < 32; k++) {
            float4 a0 = *(const float4*)&As[k * 132 + tm * 8];
            float4 a1 = *(const float4*)&As[k * 132 + tm * 8 + 4];
            ulonglong2 bb01 = *(const ulonglong2*)&Bs[k * 128 + tn * 8];
            ulonglong2 bb23 = *(const ulonglong2*)&Bs[k * 128 + tn * 8 + 4];
            float av[8] = {a0.x, a0.y, a0.z, a0.w, a1.x, a1.y, a1.z, a1.w};
#pragma unroll
            for (int i = 0; i < 8; i++) {
                unsigned long long a2 = pack2(av[i], av[i]);
                fma2(acc[i][0], a2, bb01.x);
                fma2(acc[i][1], a2, bb01.y);
                fma2(acc[i][2], a2, bb23.x);
                fma2(acc[i][3], a2, bb23.y);
            }
        }
        __syncthreads();
    }

    float bv[8];
#pragma unroll
    for (int j = 0; j < 8; j++) bv[j] = bias[l * 1024 + col0 + tn * 8 + j];
#pragma unroll
    for (int i = 0; i < 8; i++) {
        float o[8];
#pragma unroll
        for (int j = 0; j < 4; j++) unpack2(acc[i][j], o[2 * j], o[2 * j + 1]);
#pragma unroll
        for (int j = 0; j < 8; j++) o[j] += bv[j];
        size_t base = ((size_t)l * MROWS + row0 + tm * 8 + i) * 1024 + col0 + tn * 8;
        __stcs((float4*)&g_pre[base],     make_float4(o[0], o[1], o[2], o[3]));
        __stcs((float4*)&g_pre[base + 4], make_float4(o[4], o[5], o[6], o[7]));
    }
}

// ---------------- kernel 2: persistent recurrence ---------------------------
// 128 CTAs = 2 layers x 8 b-octets (8 b) x 8 hcol-groups (32 hcols).
// Barrier per (layer, b-octet): only 8 CTAs sync; staging = 8 KB.
// 256 threads = 8 warps. warp o = hcol-quad-octet; lane = ks(3b)|hq(2b).
// hcol = hcol0 + o*4 + hq. Thread: 8 b x 4 gates x 32 k, W in REGISTERS.
// Reduce-scatter over ks -> lane owns b = b0 + ks.
__global__ __launch_bounds__(256, 1) void k_rec(const float* __restrict__ h0,
                                                const float* __restrict__ c0,
                                                const float* __restrict__ W,
                                                float* __restrict__ out) {
    __shared__ __align__(16) float h_s[8 * HS_SL];   // 8320 B

    int bid   = blockIdx.x;
    int l     = bid >> 6;
    int r     = bid & 63;
    int bR    = r >> 3;                 // b-octet 0..7
    int hR    = r & 7;                  // hcol-group 0..7
    int b0    = bR << 3;
    int hcol0 = hR << 5;
    int tid   = threadIdx.x;
    int o     = tid >> 5;               // warp
    int lane  = tid & 31;
    int ks    = lane >> 2;              // 0..7 (32-k slice)
    int hq    = lane & 3;
    int hcol  = hcol0 + (o << 2) + hq;  // global hidden index
    int b_pw  = b0 + ks;                // this lane's pointwise batch row
    unsigned* cnt = &g_cnt2[l * 8 + bR][0];

    // ---- W slice -> registers (persistent across all 2048 steps) ----
    unsigned long long wfi[32], wgo[32];
    {
        const float* Whl = W + (size_t)l * 512 * 1024 + (size_t)256 * 1024;
#pragma unroll
        for (int kk = 0; kk < 32; kk++) {
            const float* wr = Whl + (size_t)((ks << 5) + kk) * 1024 + hcol;
            wfi[kk] = pack2(wr[0], wr[256]);     // (f, i)
            wgo[kk] = pack2(wr[512], wr[768]);   // (g, o)
        }
    }

    // stage h0 slice [j][b'=0..7] -> swizzled smem
    const float* h0l = h0 + l * BATCH * HID;
    for (int i = tid; i < 2048; i += 256) {
        int j  = i >> 3;
        int bp = i & 7;
        h_s[(j >> 5) * HS_SL + (j & 31) * 8 + bp] = h0l[(b0 + bp) * 256 + j];
    }
    float c = c0[l * BATCH * HID + b_pw * 256 + hcol];
    float h_cur = 0.0f;
    __syncthreads();

    const float* hp = h_s + ks * HS_SL;

    for (int t = 0; t < T_STEPS; t++) {
        // prefetch pre-activations (independent of everything below)
        size_t prow = ((size_t)l * MROWS + (size_t)t * BATCH + b_pw) * 1024 + hcol;
        float pf = __ldcs(&g_pre[prow]);
        float pi = __ldcs(&g_pre[prow + 256]);
        float pg = __ldcs(&g_pre[prow + 512]);
        float po = __ldcs(&g_pre[prow + 768]);

        // 8b partial dot over this thread's 32-k slice; W from registers
        unsigned long long fi[8], go[8];
#pragma unroll
        for (int i = 0; i < 8; i++) { fi[i] = 0ULL; go[i] = 0ULL; }
#pragma unroll
        for (int kk = 0; kk < 32; kk++) {
            float4 hv0 = *(const float4*)&hp[kk << 3];
            float4 hv1 = *(const float4*)&hp[(kk << 3) + 4];
            float hh[8] = {hv0.x, hv0.y, hv0.z, hv0.w,
                           hv1.x, hv1.y, hv1.z, hv1.w};
#pragma unroll
            for (int bi = 0; bi < 8; bi++) {
                unsigned long long a2 = pack2(hh[bi], hh[bi]);
                fma2(fi[bi], a2, wfi[kk]);
                fma2(go[bi], a2, wgo[kk]);
            }
        }

        // reduce-scatter over ks (lane strides 16,8,4): lane ends with bi=ks
#pragma unroll
        for (int rd = 0; rd < 3; rd++) {
            int stride = 16 >> rd;     // 16, 8, 4
            int half   = 4 >> rd;      // 4, 2, 1
            bool hi = (lane & stride) != 0;
#pragma unroll
            for (int i = 0; i < 4; i++) {
                if (i < half) {
                    unsigned long long sf = hi ? fi[i] : fi[i + half];
                    unsigned long long kf = hi ? fi[i + half] : fi[i];
                    fi[i] = add2(kf, __shfl_xor_sync(0xFFFFFFFFu, sf, stride));
                    unsigned long long sg = hi ? go[i] : go[i + half];
                    unsigned long long kg = hi ? go[i + half] : go[i];
                    go[i] = add2(kg, __shfl_xor_sync(0xFFFFFFFFu, sg, stride));
                }
            }
        }

        // pointwise (every lane owns one (b_pw, hcol)) — MUFU activations
        float af, ai_, ag, ao;
        unpack2(fi[0], af, ai_);
        unpack2(go[0], ag, ao);
        float gf  = fast_sigmoid(af + pf);
        float gi  = fast_sigmoid(ai_ + pi);
        float gg  = fast_tanh(ag + pg);
        float go_ = fast_sigmoid(ao + po);
        c     = gf * c + gi * gg;
        h_cur = go_ * fast_tanh(c);

        int wb = 1 - (t & 1);
        g_h2[l][wb][bR][hcol * 8 + ks] = h_cur;     // [j][b'] slice
        if (l == 1)
            __stcs(&out[(size_t)t * BATCH * HID + b_pw * 256 + hcol], h_cur);

        if (t == T_STEPS - 1) break;

        __syncthreads();
        if (tid == 0) {
            asm volatile("red.release.gpu.global.add.u32 [%0], %1;"
                         :: "l"(cnt), "r"(1u) : "memory");
            unsigned target = 8u * (unsigned)(t + 1);
            unsigned v;
            do {
                asm volatile("ld.acquire.gpu.global.u32 %0, [%1];"
                             : "=r"(v) : "l"(cnt) : "memory");
            } while (v < target);
        }
        __syncthreads();

        // stage this b-octet's h slice: contiguous 8 KB, 2 float4/thread
        const float4* src = (const float4*)g_h2[l][wb][bR];
#pragma unroll
        for (int q = 0; q < 2; q++) {
            int m  = tid + (q << 8);            // float4 index 0..511
            int j  = m >> 1;                    // hidden row 0..255
            int hf = (m & 1) << 2;              // b' half (0 or 4)
            float4 v4 = __ldcg(&src[m]);
            *(float4*)&h_s[(j >> 5) * HS_SL + (j & 31) * 8 + hf] = v4;
        }
        __syncthreads();
    }

    size_t OUTH = (size_t)T_STEPS * BATCH * HID;
    out[OUTH + (size_t)l * BATCH * HID + b_pw * 256 + hcol]                = h_cur;
    out[OUTH + (size_t)NLAYER * BATCH * HID + (size_t)l * BATCH * HID
        + b_pw * 256 + hcol]                                                = c;
}

// ---------------- launch ----------------------------------------------------
extern "C" void kernel_launch(void* const* d_in, const int* in_sizes, int n_in,
                              void* d_out, int out_size) {
    const float* x    = (const float*)d_in[0];
    const float* h0   = (const float*)d_in[1];
    const float* c0   = (const float*)d_in[2];
    const float* W    = (const float*)d_in[3];
    const float* bias = (const float*)d_in[4];
    float* out = (float*)d_out;

    k_pre<<<NLAYER * (MROWS / 128) * (1024 / 128), 256>>>(x, W, bias);
    k_rec<<<NLAYER * 64, 256>>>(h0, c0, W, out);
}